// round 5
// baseline (speedup 1.0000x reference)
#include <cuda_runtime.h>
#include <cuda_bf16.h>
#include <math.h>

// Problem constants (fixed by reference)
#define B_      16
#define T_      8192
#define D_      512
#define H_      8
#define HD_     64
#define K_      4
#define TROWS_  16
#define TB_     (T_/TROWS_)       // 512 tiles per batch
#define TSTRIDE_ 516
#define NTHR_   256

// One balanced wave at 3 CTAs/SM on 152 SMs.
#define G_      456
#define GB_HI_  29
#define GB_LO_  28
#define C_HI_   (8*GB_HI_)        // 232

#define SM_TILE_F (TROWS_*TSTRIDE_)   // 8256 floats per buffer
#define SM_Q_F    (K_*D_)             // 2048
#define SM_P_F    (H_*TROWS_*K_)      // 512
#define SMEM_BYTES ((2*SM_TILE_F + SM_Q_F + SM_P_F)*4 + 2*TROWS_*4)  // 76416 B

// ---------------- device scratch (no allocations allowed) ----------------
__device__ __align__(16) float g_l  [G_*H_*K_];
__device__ __align__(16) float g_acc[G_*H_*K_*HD_];

// ---------------- packed fp32x2 FMA (Blackwell) ----------------
union F2U { float2 f; unsigned long long u; };
__device__ __forceinline__ float2 ffma2(float2 a, float2 b, float2 c) {
    F2U A, Bv, C, Dv;
    A.f = a; Bv.f = b; C.f = c;
    asm("fma.rn.f32x2 %0, %1, %2, %3;" : "=l"(Dv.u) : "l"(A.u), "l"(Bv.u), "l"(C.u));
    return Dv.f;
}

#define CP_COMMIT() asm volatile("cp.async.commit_group;")
#define CP_WAIT1()  asm volatile("cp.async.wait_group 1;")
#define CP_WAIT0()  asm volatile("cp.async.wait_group 0;")

__device__ __forceinline__ void cp16(float* dst_sh, const void* src) {
    unsigned d = (unsigned)__cvta_generic_to_shared(dst_sh);
    asm volatile("cp.async.cg.shared.global [%0], [%1], 16;" :: "r"(d), "l"(src));
}

// issue one 16x512 tile (+16 mask ints) into a buffer via cp.async
__device__ __forceinline__ void issue_tile(const float* __restrict__ src,
                                           float* __restrict__ dst,
                                           const int* __restrict__ msrc,
                                           int* __restrict__ mdst, int tid)
{
    #pragma unroll
    for (int it = 0; it < 8; it++) {
        int f   = tid + NTHR_ * it;     // 0..2047
        int row = f >> 7;               // 0..15
        int c4  = f & 127;
        cp16(dst + row * TSTRIDE_ + c4 * 4, src + (long)row * D_ + c4 * 4);
    }
    if (tid < 4) cp16((float*)(mdst + tid * 4), msrc + tid * 4);
}

// ======================================================================
// Kernel 1: pipelined attention pooling, fixed softmax shift (m = 0).
// q in SMEM (broadcast LDS), 3 CTAs/SM, one balanced wave.
// ======================================================================
__global__ void __launch_bounds__(NTHR_, 3)
attn_main(const float* __restrict__ x, const int* __restrict__ mask,
          const float* __restrict__ queries)
{
    extern __shared__ float sm[];
    float* q_sh  = sm + 2 * SM_TILE_F;         // [K][D]
    float* p_sh  = q_sh + SM_Q_F;              // [H][16][K]
    int*   mbase = (int*)(p_sh + SM_P_F);      // [2][16]

    const int c    = blockIdx.x;
    const int tid  = threadIdx.x;
    const int w    = tid >> 5;                 // warp == head
    const int lane = tid & 31;
    const int row  = lane >> 1;                // phase-1 row (0..15)
    const int half = lane & 1;                 // which 32-dim half

    int b, j, Gb;
    if (c < C_HI_) { b = c / GB_HI_; j = c % GB_HI_; Gb = GB_HI_; }
    else { int c2 = c - C_HI_; b = 8 + c2 / GB_LO_; j = c2 % GB_LO_; Gb = GB_LO_; }
    const int tstart = (j * TB_) / Gb;
    const int ntiles = ((j + 1) * TB_) / Gb - tstart;

    const float* xb = x + ((long)b * T_ + (long)tstart * TROWS_) * D_;
    const int*   mb = mask + (long)b * T_ + tstart * TROWS_;

    // queries -> shared once
    #pragma unroll
    for (int i = tid; i < SM_Q_F/4; i += NTHR_)
        *reinterpret_cast<float4*>(q_sh + i*4) =
            *reinterpret_cast<const float4*>(queries + i*4);

    float  l[K_];
    float2 acc[K_];
    #pragma unroll
    for (int k = 0; k < K_; k++) { l[k] = 0.f; acc[k] = make_float2(0.f, 0.f); }

    // prologue
    issue_tile(xb, sm, mb, mbase, tid);
    CP_COMMIT();
    if (ntiles > 1) {
        issue_tile(xb + (long)TROWS_ * D_, sm + SM_TILE_F, mb + TROWS_, mbase + TROWS_, tid);
        CP_COMMIT();
    }

    for (int tl = 0; tl < ntiles; tl++) {
        if (tl + 1 < ntiles) CP_WAIT1(); else CP_WAIT0();
        __syncthreads();                       // tile tl visible (q_sh too on tl=0)

        const float* tile = sm + (tl & 1) * SM_TILE_F;
        const int*   msk  = mbase + (tl & 1) * TROWS_;

        // ---- phase 1: lane pair = row; each lane does 32 dims ----
        float2 sk[K_];
        #pragma unroll
        for (int k = 0; k < K_; k++) sk[k] = make_float2(0.f, 0.f);
        const float* vrow = tile + row * TSTRIDE_ + w * HD_ + half * 32;
        const float* qh   = q_sh + w * HD_ + half * 32;
        #pragma unroll
        for (int i4 = 0; i4 < 8; i4++) {
            int j4 = (i4 + half) & 7;          // phase shift: conflict-free
            float4 v4 = *reinterpret_cast<const float4*>(vrow + j4 * 4);
            float2 va = make_float2(v4.x, v4.y);
            float2 vb = make_float2(v4.z, v4.w);
            #pragma unroll
            for (int k = 0; k < K_; k++) {
                float4 q4 = *reinterpret_cast<const float4*>(qh + k * D_ + j4 * 4);
                sk[k] = ffma2(va, make_float2(q4.x, q4.y), sk[k]);
                sk[k] = ffma2(vb, make_float2(q4.z, q4.w), sk[k]);
            }
        }
        const int mv = msk[row];
        float p[K_];
        #pragma unroll
        for (int k = 0; k < K_; k++) {
            float v = sk[k].x + sk[k].y;
            v += __shfl_xor_sync(0xffffffffu, v, 1);   // combine halves
            p[k] = (mv == 0) ? 0.f : __expf(v * 0.125f);
            l[k] += p[k];
        }
        if (half == 0)
            *reinterpret_cast<float4*>(p_sh + (w * TROWS_ + row) * K_) =
                make_float4(p[0], p[1], p[2], p[3]);
        __syncwarp();

        // ---- phase 2: lane owns d = {2*lane, 2*lane+1} of this head ----
        const float* base2 = tile + w * HD_ + 2 * lane;
        const float* pb    = p_sh + w * TROWS_ * K_;
        #pragma unroll
        for (int t = 0; t < TROWS_; t++) {
            float2 v2 = *reinterpret_cast<const float2*>(base2 + t * TSTRIDE_);
            float4 p4 = *reinterpret_cast<const float4*>(pb + t * K_);
            acc[0] = ffma2(v2, make_float2(p4.x, p4.x), acc[0]);
            acc[1] = ffma2(v2, make_float2(p4.y, p4.y), acc[1]);
            acc[2] = ffma2(v2, make_float2(p4.z, p4.z), acc[2]);
            acc[3] = ffma2(v2, make_float2(p4.w, p4.w), acc[3]);
        }
        __syncthreads();                       // all done reading buf (tl&1)

        if (tl + 2 < ntiles) {
            issue_tile(xb + (long)(tl + 2) * TROWS_ * D_, sm + (tl & 1) * SM_TILE_F,
                       mb + (tl + 2) * TROWS_, mbase + (tl & 1) * TROWS_, tid);
            CP_COMMIT();
        }
    }

    // ---- reduce l across lanes (each row counted twice -> *0.5) ----
    #pragma unroll
    for (int k = 0; k < K_; k++) {
        float v = l[k];
        #pragma unroll
        for (int off = 16; off > 0; off >>= 1)
            v += __shfl_xor_sync(0xffffffffu, v, off);
        l[k] = v * 0.5f;
    }

    const long idxBase = ((long)c * H_ + w) * K_;
    if (lane == 0) {
        #pragma unroll
        for (int k = 0; k < K_; k++) g_l[idxBase + k] = l[k];
    }
    #pragma unroll
    for (int k = 0; k < K_; k++)
        *reinterpret_cast<float2*>(&g_acc[(idxBase + k) * HD_ + 2 * lane]) = acc[k];
}

// ======================================================================
// Kernel 2 (fused): combine split partials + linear projection.
// grid (8 rowgroups of 8 rows, 8 jgroups of 64 cols), 256 thr.
// ======================================================================
__global__ void __launch_bounds__(256)
epi_k(const float* __restrict__ w_out, const float* __restrict__ b_out,
      float* __restrict__ out)
{
    __shared__ __align__(16) float ps[8][D_];
    __shared__ float slt[8][H_];
    const int rg  = blockIdx.x;             // rows rg*8..rg*8+7  (row = b*K + k)
    const int jg  = blockIdx.y;
    const int tid = threadIdx.x;

    // ---- per-(row, head) softmax denominators ----
    if (tid < 64) {
        int r = tid >> 3, h = tid & 7;
        int R = rg * 8 + r, b = R >> 2, k = R & 3;
        int base, Gb;
        if (b < 8) { base = b * GB_HI_; Gb = GB_HI_; }
        else       { base = C_HI_ + (b - 8) * GB_LO_; Gb = GB_LO_; }
        float lt = 0.f;
        #pragma unroll 4
        for (int s = 0; s < Gb; s++)
            lt += g_l[((long)(base + s) * H_ + h) * K_ + k];
        slt[r][h] = lt;
    }
    __syncthreads();

    // ---- pooled rows: sum split accumulators, divide by lt ----
    for (int i = tid; i < 8 * D_; i += 256) {
        int r = i >> 9, col = i & 511;
        int h = col >> 6, d = col & 63;
        int R = rg * 8 + r, b = R >> 2, k = R & 3;
        int base, Gb;
        if (b < 8) { base = b * GB_HI_; Gb = GB_HI_; }
        else       { base = C_HI_ + (b - 8) * GB_LO_; Gb = GB_LO_; }
        float a = 0.f;
        #pragma unroll 4
        for (int s = 0; s < Gb; s++)
            a += g_acc[(((long)(base + s) * H_ + h) * K_ + k) * HD_ + d];
        ps[r][col] = a / slt[r][h];
    }
    __syncthreads();

    // ---- GEMM: each thread does 1 j x 2 rows ----
    const int jl = tid & 63;
    const int rp = tid >> 6;                // rows rp*2, rp*2+1
    const int j  = jg * 64 + jl;
    const float* wr = w_out + (long)j * D_;

    float2 a0 = make_float2(0.f, 0.f), a1 = make_float2(0.f, 0.f);
    #pragma unroll 8
    for (int i4 = 0; i4 < D_/4; i4++) {
        float4 wv = *reinterpret_cast<const float4*>(wr + i4 * 4);
        float4 p0 = *reinterpret_cast<const float4*>(&ps[rp*2    ][i4*4]);
        float4 p1 = *reinterpret_cast<const float4*>(&ps[rp*2 + 1][i4*4]);
        a0 = ffma2(make_float2(wv.x, wv.y), make_float2(p0.x, p0.y), a0);
        a0 = ffma2(make_float2(wv.z, wv.w), make_float2(p0.z, p0.w), a0);
        a1 = ffma2(make_float2(wv.x, wv.y), make_float2(p1.x, p1.y), a1);
        a1 = ffma2(make_float2(wv.z, wv.w), make_float2(p1.z, p1.w), a1);
    }
    float bj = b_out[j];
    out[(long)(rg*8 + rp*2    ) * D_ + j] = bj + a0.x + a0.y;
    out[(long)(rg*8 + rp*2 + 1) * D_ + j] = bj + a1.x + a1.y;
}

// ======================================================================
extern "C" void kernel_launch(void* const* d_in, const int* in_sizes, int n_in,
                              void* d_out, int out_size)
{
    const float* x       = (const float*)d_in[0];
    const int*   mask    = (const int*)  d_in[1];
    const float* queries = (const float*)d_in[2];
    const float* w_out   = (const float*)d_in[3];
    const float* b_out   = (const float*)d_in[4];
    float* out = (float*)d_out;

    cudaFuncSetAttribute((const void*)attn_main,
                         cudaFuncAttributeMaxDynamicSharedMemorySize, SMEM_BYTES);

    attn_main<<<G_, NTHR_, SMEM_BYTES>>>(x, mask, queries);
    epi_k<<<dim3(8, 8), 256>>>(w_out, b_out, out);
}

// round 6
// speedup vs baseline: 1.3768x; 1.3768x over previous
#include <cuda_runtime.h>
#include <cuda_bf16.h>
#include <math.h>

// Problem constants (fixed by reference)
#define B_      16
#define T_      8192
#define D_      512
#define H_      8
#define HD_     64
#define K_      4
#define TROWS_  16
#define TB_     (T_/TROWS_)       // 512 tiles per batch
#define TSTRIDE_ 516
#define NTHR_   256

// One balanced wave at 3 CTAs/SM on 152 SMs.
#define G_      456
#define GB_HI_  29
#define GB_LO_  28
#define C_HI_   (8*GB_HI_)        // 232

#define SM_TILE_F (TROWS_*TSTRIDE_)   // 8256 floats per buffer
#define SM_Q_F    (K_*D_)             // 2048
#define SM_P_F    (H_*TROWS_*K_)      // 512
#define SMEM_BYTES ((2*SM_TILE_F + SM_Q_F + SM_P_F)*4 + 2*TROWS_*4)  // 76416 B

// ---------------- device scratch (no allocations allowed) ----------------
__device__ __align__(16) float g_pool[B_*K_*D_];     // atomic accumulators
__device__ __align__(16) float g_lsum[B_*K_*H_];     // atomic denominators

// ---------------- packed fp32x2 FMA (Blackwell) ----------------
union F2U { float2 f; unsigned long long u; };
__device__ __forceinline__ float2 ffma2(float2 a, float2 b, float2 c) {
    F2U A, Bv, C, Dv;
    A.f = a; Bv.f = b; C.f = c;
    asm("fma.rn.f32x2 %0, %1, %2, %3;" : "=l"(Dv.u) : "l"(A.u), "l"(Bv.u), "l"(C.u));
    return Dv.f;
}

#define CP_COMMIT() asm volatile("cp.async.commit_group;")
#define CP_WAIT1()  asm volatile("cp.async.wait_group 1;")
#define CP_WAIT0()  asm volatile("cp.async.wait_group 0;")

__device__ __forceinline__ void cp16(float* dst_sh, const void* src) {
    unsigned d = (unsigned)__cvta_generic_to_shared(dst_sh);
    asm volatile("cp.async.cg.shared.global [%0], [%1], 16;" :: "r"(d), "l"(src));
}

// issue one 16x512 tile (+16 mask ints) into a buffer via cp.async
__device__ __forceinline__ void issue_tile(const float* __restrict__ src,
                                           float* __restrict__ dst,
                                           const int* __restrict__ msrc,
                                           int* __restrict__ mdst, int tid)
{
    #pragma unroll
    for (int it = 0; it < 8; it++) {
        int f   = tid + NTHR_ * it;     // 0..2047
        int row = f >> 7;               // 0..15
        int c4  = f & 127;
        cp16(dst + row * TSTRIDE_ + c4 * 4, src + (long)row * D_ + c4 * 4);
    }
    if (tid < 4) cp16((float*)(mdst + tid * 4), msrc + tid * 4);
}

// ======================================================================
// Kernel 0: zero the atomic accumulators
// ======================================================================
__global__ void zero_k()
{
    int i = blockIdx.x * 256 + threadIdx.x;
    if (i < B_*K_*D_) g_pool[i] = 0.f;
    if (i < B_*K_*H_) g_lsum[i] = 0.f;
}

// ======================================================================
// Kernel 1: pipelined attention pooling, fixed softmax shift (m = 0).
// q in SMEM (broadcast LDS), 3 CTAs/SM, one balanced wave.
// Tail: atomic accumulation into g_pool / g_lsum (plain sums, m=0).
// ======================================================================
__global__ void __launch_bounds__(NTHR_, 3)
attn_main(const float* __restrict__ x, const int* __restrict__ mask,
          const float* __restrict__ queries)
{
    extern __shared__ float sm[];
    float* q_sh  = sm + 2 * SM_TILE_F;         // [K][D]
    float* p_sh  = q_sh + SM_Q_F;              // [H][16][K]
    int*   mbase = (int*)(p_sh + SM_P_F);      // [2][16]

    const int c    = blockIdx.x;
    const int tid  = threadIdx.x;
    const int w    = tid >> 5;                 // warp == head
    const int lane = tid & 31;
    const int row  = lane >> 1;                // phase-1 row (0..15)
    const int half = lane & 1;                 // which 32-dim half

    int b, j, Gb;
    if (c < C_HI_) { b = c / GB_HI_; j = c % GB_HI_; Gb = GB_HI_; }
    else { int c2 = c - C_HI_; b = 8 + c2 / GB_LO_; j = c2 % GB_LO_; Gb = GB_LO_; }
    const int tstart = (j * TB_) / Gb;
    const int ntiles = ((j + 1) * TB_) / Gb - tstart;

    const float* xb = x + ((long)b * T_ + (long)tstart * TROWS_) * D_;
    const int*   mb = mask + (long)b * T_ + tstart * TROWS_;

    // queries -> shared once
    #pragma unroll
    for (int i = tid; i < SM_Q_F/4; i += NTHR_)
        *reinterpret_cast<float4*>(q_sh + i*4) =
            *reinterpret_cast<const float4*>(queries + i*4);

    float  l[K_];
    float2 acc[K_];
    #pragma unroll
    for (int k = 0; k < K_; k++) { l[k] = 0.f; acc[k] = make_float2(0.f, 0.f); }

    // prologue
    issue_tile(xb, sm, mb, mbase, tid);
    CP_COMMIT();
    if (ntiles > 1) {
        issue_tile(xb + (long)TROWS_ * D_, sm + SM_TILE_F, mb + TROWS_, mbase + TROWS_, tid);
        CP_COMMIT();
    }

    for (int tl = 0; tl < ntiles; tl++) {
        if (tl + 1 < ntiles) CP_WAIT1(); else CP_WAIT0();
        __syncthreads();                       // tile tl visible (q_sh too on tl=0)

        const float* tile = sm + (tl & 1) * SM_TILE_F;
        const int*   msk  = mbase + (tl & 1) * TROWS_;

        // ---- phase 1: lane pair = row; each lane does 32 dims ----
        float2 sk[K_];
        #pragma unroll
        for (int k = 0; k < K_; k++) sk[k] = make_float2(0.f, 0.f);
        const float* vrow = tile + row * TSTRIDE_ + w * HD_ + half * 32;
        const float* qh   = q_sh + w * HD_ + half * 32;
        #pragma unroll
        for (int i4 = 0; i4 < 8; i4++) {
            int j4 = (i4 + half) & 7;          // phase shift: conflict-free
            float4 v4 = *reinterpret_cast<const float4*>(vrow + j4 * 4);
            float2 va = make_float2(v4.x, v4.y);
            float2 vb = make_float2(v4.z, v4.w);
            #pragma unroll
            for (int k = 0; k < K_; k++) {
                float4 q4 = *reinterpret_cast<const float4*>(qh + k * D_ + j4 * 4);
                sk[k] = ffma2(va, make_float2(q4.x, q4.y), sk[k]);
                sk[k] = ffma2(vb, make_float2(q4.z, q4.w), sk[k]);
            }
        }
        const int mv = msk[row];
        float p[K_];
        #pragma unroll
        for (int k = 0; k < K_; k++) {
            float v = sk[k].x + sk[k].y;
            v += __shfl_xor_sync(0xffffffffu, v, 1);   // combine halves
            p[k] = (mv == 0) ? 0.f : __expf(v * 0.125f);
            l[k] += p[k];
        }
        if (half == 0)
            *reinterpret_cast<float4*>(p_sh + (w * TROWS_ + row) * K_) =
                make_float4(p[0], p[1], p[2], p[3]);
        __syncwarp();

        // ---- phase 2: lane owns d = {2*lane, 2*lane+1} of this head ----
        const float* base2 = tile + w * HD_ + 2 * lane;
        const float* pb    = p_sh + w * TROWS_ * K_;
        #pragma unroll
        for (int t = 0; t < TROWS_; t++) {
            float2 v2 = *reinterpret_cast<const float2*>(base2 + t * TSTRIDE_);
            float4 p4 = *reinterpret_cast<const float4*>(pb + t * K_);
            acc[0] = ffma2(v2, make_float2(p4.x, p4.x), acc[0]);
            acc[1] = ffma2(v2, make_float2(p4.y, p4.y), acc[1]);
            acc[2] = ffma2(v2, make_float2(p4.z, p4.z), acc[2]);
            acc[3] = ffma2(v2, make_float2(p4.w, p4.w), acc[3]);
        }
        __syncthreads();                       // all done reading buf (tl&1)

        if (tl + 2 < ntiles) {
            issue_tile(xb + (long)(tl + 2) * TROWS_ * D_, sm + (tl & 1) * SM_TILE_F,
                       mb + (tl + 2) * TROWS_, mbase + (tl & 1) * TROWS_, tid);
            CP_COMMIT();
        }
    }

    // ---- reduce l across lanes (each row counted twice -> *0.5) ----
    #pragma unroll
    for (int k = 0; k < K_; k++) {
        float v = l[k];
        #pragma unroll
        for (int off = 16; off > 0; off >>= 1)
            v += __shfl_xor_sync(0xffffffffu, v, off);
        l[k] = v * 0.5f;
    }

    // ---- atomic tail: plain sums across CTAs (m = 0 everywhere) ----
    if (lane == 0) {
        #pragma unroll
        for (int k = 0; k < K_; k++)
            atomicAdd(&g_lsum[((long)b * K_ + k) * H_ + w], l[k]);
    }
    #pragma unroll
    for (int k = 0; k < K_; k++) {
        float* dst = &g_pool[((long)b * K_ + k) * D_ + w * HD_ + 2 * lane];
        atomicAdd(dst,     acc[k].x);
        atomicAdd(dst + 1, acc[k].y);
    }
}

// ======================================================================
// Kernel 2: normalize pooled rows + linear projection.
// grid (8 rowgroups of 8 rows, 8 jgroups of 64 cols), 256 thr.
// ======================================================================
__global__ void __launch_bounds__(256)
epi_k(const float* __restrict__ w_out, const float* __restrict__ b_out,
      float* __restrict__ out)
{
    __shared__ __align__(16) float ps[8][D_];
    __shared__ float slt[8][H_];
    const int rg  = blockIdx.x;             // rows rg*8..rg*8+7  (row = b*K + k)
    const int jg  = blockIdx.y;
    const int tid = threadIdx.x;

    if (tid < 64) {
        int r = tid >> 3, h = tid & 7;
        slt[r][h] = g_lsum[(long)(rg * 8 + r) * H_ + h];
    }
    __syncthreads();

    for (int i = tid; i < 8 * D_; i += 256) {
        int r = i >> 9, col = i & 511;
        ps[r][col] = g_pool[(long)(rg * 8 + r) * D_ + col] / slt[r][col >> 6];
    }
    __syncthreads();

    const int jl = tid & 63;
    const int rp = tid >> 6;                // rows rp*2, rp*2+1
    const int j  = jg * 64 + jl;
    const float* wr = w_out + (long)j * D_;

    float2 a0 = make_float2(0.f, 0.f), a1 = make_float2(0.f, 0.f);
    #pragma unroll 8
    for (int i4 = 0; i4 < D_/4; i4++) {
        float4 wv = *reinterpret_cast<const float4*>(wr + i4 * 4);
        float4 p0 = *reinterpret_cast<const float4*>(&ps[rp*2    ][i4*4]);
        float4 p1 = *reinterpret_cast<const float4*>(&ps[rp*2 + 1][i4*4]);
        a0 = ffma2(make_float2(wv.x, wv.y), make_float2(p0.x, p0.y), a0);
        a0 = ffma2(make_float2(wv.z, wv.w), make_float2(p0.z, p0.w), a0);
        a1 = ffma2(make_float2(wv.x, wv.y), make_float2(p1.x, p1.y), a1);
        a1 = ffma2(make_float2(wv.z, wv.w), make_float2(p1.z, p1.w), a1);
    }
    float bj = b_out[j];
    out[(long)(rg*8 + rp*2    ) * D_ + j] = bj + a0.x + a0.y;
    out[(long)(rg*8 + rp*2 + 1) * D_ + j] = bj + a1.x + a1.y;
}

// ======================================================================
extern "C" void kernel_launch(void* const* d_in, const int* in_sizes, int n_in,
                              void* d_out, int out_size)
{
    const float* x       = (const float*)d_in[0];
    const int*   mask    = (const int*)  d_in[1];
    const float* queries = (const float*)d_in[2];
    const float* w_out   = (const float*)d_in[3];
    const float* b_out   = (const float*)d_in[4];
    float* out = (float*)d_out;

    cudaFuncSetAttribute((const void*)attn_main,
                         cudaFuncAttributeMaxDynamicSharedMemorySize, SMEM_BYTES);

    zero_k<<<(B_*K_*D_ + 255) / 256, 256>>>();
    attn_main<<<G_, NTHR_, SMEM_BYTES>>>(x, mask, queries);
    epi_k<<<dim3(8, 8), 256>>>(w_out, b_out, out);
}